// round 14
// baseline (speedup 1.0000x reference)
#include <cuda_runtime.h>
#include <cuda_bf16.h>
#include <cstdint>

#define D       128
#define BM      32          // rows per x tile
#define NTHR    256         // 8 warps
#define RSTRIDE 272         // padded smem row stride (17 x 16B) -> conflict-free ldmatrix
#define SSTRIDE 132         // out-stage row stride in floats (528 B)

#define XBUF    (BM * RSTRIDE)        // 8704 bytes, one XH or XL tile
#define RAWSZ   (BM * D * 4)          // 16384 bytes raw fp32 tile
// ---------------- smem layout (bytes) ----------------
#define OFF_LAM  0                    // 2 x 32 floats (double-buffered)
#define OFF_CA   256
#define OFF_CB   768
#define OFF_CC   1280
#define OFF_ZSQ  1792
#define OFF_RAW  2304                 // raw fp32 x tiles, 2 x 16KB
#define OFF_X    (OFF_RAW + 2 * RAWSZ)  // XH0,XL0,XH1,XL1 each XBUF
#define OFF_STAGE (OFF_X + 4 * XBUF)    // fp32 out stage, 32 x 528 B
#define SMEM_TOTAL (OFF_STAGE + BM * SSTRIDE * 4)  // 86784 B -> 2 CTAs/SM
// Z staging at startup aliases the X region (4*XBUF == one 128x272 Z tile)

__device__ __forceinline__ uint32_t smem_u32(const void* p) {
    uint32_t a;
    asm("{ .reg .u64 t; cvta.to.shared.u64 t, %1; cvt.u32.u64 %0, t; }" : "=r"(a) : "l"(p));
    return a;
}
#define CP_ASYNC16(s, g) \
    asm volatile("cp.async.cg.shared.global [%0], [%1], 16;" :: "r"(s), "l"(g) : "memory")
#define CP_COMMIT() asm volatile("cp.async.commit_group;" ::: "memory")
#define CP_WAIT1()  asm volatile("cp.async.wait_group 1;" ::: "memory")

#define LDMATRIX_X4(r0, r1, r2, r3, a)                                           \
    asm volatile("ldmatrix.sync.aligned.m8n8.x4.shared.b16 {%0,%1,%2,%3}, [%4];" \
                 : "=r"(r0), "=r"(r1), "=r"(r2), "=r"(r3) : "r"(a))

#define MMA16816(d, a0, a1, a2, a3, b0, b1)                                      \
    asm volatile("mma.sync.aligned.m16n8k16.row.col.f32.bf16.bf16.f32 "          \
                 "{%0,%1,%2,%3}, {%4,%5,%6,%7}, {%8,%9}, {%0,%1,%2,%3};"         \
                 : "+f"((d)[0]), "+f"((d)[1]), "+f"((d)[2]), "+f"((d)[3])        \
                 : "r"(a0), "r"(a1), "r"(a2), "r"(a3), "r"(b0), "r"(b1))

__device__ __forceinline__ float sqrt_approx(float v) {
    float o;
    asm("sqrt.approx.f32 %0, %1;" : "=f"(o) : "f"(v));
    return o;
}
__device__ __forceinline__ float asinh_fast(float v) {
    float av = fabsf(v);
    float s  = sqrt_approx(fmaf(av, av, 1.0f));
    float l  = __logf(av + s);
    return copysignf(l, v);
}

// ---------------------------------------------------------------------------
// Persistent fused kernel, 2 CTAs/SM x 8 warps. Warp tile m32 x n16, B hi+lo
// hoisted to regs, RAW + XH/XL double-buffered. Epilogue stages the fp32
// output tile in padded SMEM and writes out with fully coalesced STG.128
// (4 lines per store inst instead of 8 scattered lines per STG.64).
//   inner = xh*zh^T + xh*zl^T + xl*zh^T  (fp32 accum, rel err ~4e-6)
// ---------------------------------------------------------------------------
__global__ __launch_bounds__(NTHR, 2)
void hmlr_fused(const float* __restrict__ x, const float* __restrict__ z,
                const float* __restrict__ r, float* __restrict__ out,
                int nTiles, int step) {
    extern __shared__ unsigned char smem[];
    const uint32_t sb = smem_u32(smem);
    const int tid  = threadIdx.x;
    const int wid  = tid >> 5;
    const int lane = tid & 31;
    const int t0   = blockIdx.x;

    // ---- kick off first two x tile loads ASAP (raw double buffer) ----
    {
        const char* xg0 = (const char*)(x + (size_t)t0 * BM * D);
        #pragma unroll
        for (int j = 0; j < 4; j++) {
            uint32_t off = (uint32_t)(tid + j * NTHR) * 16u;
            CP_ASYNC16(sb + OFF_RAW + off, xg0 + off);
        }
        CP_COMMIT();
        if (t0 + step < nTiles) {
            const char* xg1 = (const char*)(x + (size_t)(t0 + step) * BM * D);
            #pragma unroll
            for (int j = 0; j < 4; j++) {
                uint32_t off = (uint32_t)(tid + j * NTHR) * 16u;
                CP_ASYNC16(sb + OFF_RAW + RAWSZ + off, xg1 + off);
            }
        }
        CP_COMMIT();
    }

    // ---- zero column-norm accumulators ----
    if (tid < D) ((float*)(smem + OFF_ZSQ))[tid] = 0.0f;
    __syncthreads();

    // ---- warp tiling: single m32 row band x 8 col bands of n16 ----
    const int cb = wid << 4;                     // 0..112
    const int g  = lane >> 3, rr = lane & 7;
    const uint32_t offA = (uint32_t)((((g & 1) << 3) + rr) * RSTRIDE + ((g >> 1) << 4));
    const uint32_t offB = (uint32_t)((cb + ((g >> 1) << 3) + rr) * RSTRIDE + ((g & 1) << 4));

    uint32_t bh[8][4], bl[8][4];

    // ---- phase 1: stage ZH (aliases X region) + column norms; hoist bh ----
    {
        const int n  = tid & 127;
        const int kh = tid >> 7;                 // 0..1, 64 k each
        float sq = 0.0f;
        #pragma unroll 8
        for (int kk = 0; kk < 64; kk++) {
            int k = kh * 64 + kk;
            float v = z[(size_t)k * D + n];
            *(__nv_bfloat16*)(smem + OFF_X + n * RSTRIDE + k * 2) = __float2bfloat16_rn(v);
            sq = fmaf(v, v, sq);
        }
        atomicAdd((float*)(smem + OFF_ZSQ) + n, sq);
    }
    __syncthreads();
    {
        const uint32_t bHb = sb + OFF_X + offB;
        #pragma unroll
        for (int ks = 0; ks < 8; ks++)
            LDMATRIX_X4(bh[ks][0], bh[ks][1], bh[ks][2], bh[ks][3], bHb + ks * 32u);
    }
    // per-column constants (ZSQ final after phase-1 barrier)
    if (tid < D) {
        float zn = fmaxf(sqrtf(((const float*)(smem + OFF_ZSQ))[tid]), 1e-15f);
        float t  = 2.0f * r[tid];
        ((float*)(smem + OFF_CA))[tid] = coshf(t) / zn;
        ((float*)(smem + OFF_CB))[tid] = sinhf(t);
        ((float*)(smem + OFF_CC))[tid] = 2.0f * zn;
    }
    __syncthreads();                              // bh hoists done before ZL overwrites

    // ---- phase 2: stage ZL into same region; hoist bl ----
    {
        const int n  = tid & 127;
        const int kh = tid >> 7;
        #pragma unroll 8
        for (int kk = 0; kk < 64; kk++) {
            int k = kh * 64 + kk;
            float v = z[(size_t)k * D + n];
            __nv_bfloat16 h = __float2bfloat16_rn(v);
            float res = v - __bfloat162float(h);
            *(__nv_bfloat16*)(smem + OFF_X + n * RSTRIDE + k * 2) = __float2bfloat16_rn(res);
        }
    }
    __syncthreads();
    {
        const uint32_t bLb = sb + OFF_X + offB;
        #pragma unroll
        for (int ks = 0; ks < 8; ks++)
            LDMATRIX_X4(bl[ks][0], bl[ks][1], bl[ks][2], bl[ks][3], bLb + ks * 32u);
    }
    // loop-top barrier orders these hoist reads before first convert stores

    float* stg = (float*)(smem + OFF_STAGE);

    // ================= persistent tile loop =================
    int p = 0;
    for (int t = t0; t < nTiles; t += step, p ^= 1) {
        const uint32_t rawB = sb + OFF_RAW + (uint32_t)p * RAWSZ;
        const uint32_t xB   = sb + OFF_X + (uint32_t)p * (2u * XBUF);
        float* lam = (float*)(smem + OFF_LAM) + p * 32;

        CP_WAIT1();
        __syncthreads();                          // raw[p] visible; hoist/old reads done

        // ---- convert raw fp32 -> bf16 hi/lo + lambda (buffer p) ----
        {
            const int row   = tid >> 3;           // 0..31
            const int chunk = tid & 7;            // 16 floats each
            const float4* rp = (const float4*)(smem + (rawB - sb) + row * 512 + chunk * 64);
            float4 v[4];
            v[0] = rp[0]; v[1] = rp[1]; v[2] = rp[2]; v[3] = rp[3];
            float f[16];
            #pragma unroll
            for (int j = 0; j < 4; j++) {
                f[4 * j] = v[j].x; f[4 * j + 1] = v[j].y;
                f[4 * j + 2] = v[j].z; f[4 * j + 3] = v[j].w;
            }
            uint32_t hp[8], lp[8];
            #pragma unroll
            for (int j = 0; j < 8; j++) {
                float a = f[2 * j], b = f[2 * j + 1];
                __nv_bfloat16 ha = __float2bfloat16_rn(a);
                __nv_bfloat16 hb = __float2bfloat16_rn(b);
                float ra = a - __bfloat162float(ha);
                float rc = b - __bfloat162float(hb);
                hp[j] = (uint32_t)__bfloat16_as_ushort(ha) |
                        ((uint32_t)__bfloat16_as_ushort(hb) << 16);
                lp[j] = (uint32_t)__bfloat16_as_ushort(__float2bfloat16_rn(ra)) |
                        ((uint32_t)__bfloat16_as_ushort(__float2bfloat16_rn(rc)) << 16);
            }
            uint32_t doff = (xB - sb) + (uint32_t)(row * RSTRIDE + chunk * 32);
            *(uint4*)(smem + doff)             = make_uint4(hp[0], hp[1], hp[2], hp[3]);
            *(uint4*)(smem + doff + 16)        = make_uint4(hp[4], hp[5], hp[6], hp[7]);
            *(uint4*)(smem + doff + XBUF)      = make_uint4(lp[0], lp[1], lp[2], lp[3]);
            *(uint4*)(smem + doff + XBUF + 16) = make_uint4(lp[4], lp[5], lp[6], lp[7]);

            float sq = 0.0f;
            #pragma unroll
            for (int j = 0; j < 16; j++) sq = fmaf(f[j], f[j], sq);
            sq += __shfl_xor_sync(0xffffffffu, sq, 1);
            sq += __shfl_xor_sync(0xffffffffu, sq, 2);
            sq += __shfl_xor_sync(0xffffffffu, sq, 4);
            if ((lane & 7) == 0) lam[row] = 2.0f / (1.0f - sq);
        }
        __syncthreads();                          // X[p]+lam ready; raw[p] reads done

        // ---- prefetch tile t+2*step into raw[p] ----
        if (t + 2 * step < nTiles) {
            const char* xg = (const char*)(x + (size_t)(t + 2 * step) * BM * D);
            #pragma unroll
            for (int j = 0; j < 4; j++) {
                uint32_t off = (uint32_t)(tid + j * NTHR) * 16u;
                CP_ASYNC16(rawB + off, xg + off);
            }
        }
        CP_COMMIT();

        // ---- MMA: A from smem buffer p, B from regs; 12 HMMA per ks ----
        const uint32_t aH0 = xB + offA;
        const uint32_t aH1 = aH0 + 16 * RSTRIDE;
        const uint32_t aL0 = aH0 + XBUF;
        const uint32_t aL1 = aL0 + 16 * RSTRIDE;

        float acc[2][2][4];
        #pragma unroll
        for (int mi = 0; mi < 2; mi++)
            #pragma unroll
            for (int ni = 0; ni < 2; ni++)
                #pragma unroll
                for (int j = 0; j < 4; j++) acc[mi][ni][j] = 0.0f;

        #pragma unroll
        for (int ks = 0; ks < 8; ks++) {
            const uint32_t kd = (uint32_t)ks * 32u;
            uint32_t a0[4], a1[4], l0[4], l1[4];
            LDMATRIX_X4(a0[0], a0[1], a0[2], a0[3], aH0 + kd);
            LDMATRIX_X4(a1[0], a1[1], a1[2], a1[3], aH1 + kd);
            LDMATRIX_X4(l0[0], l0[1], l0[2], l0[3], aL0 + kd);
            LDMATRIX_X4(l1[0], l1[1], l1[2], l1[3], aL1 + kd);
            // hi * hi
            MMA16816(acc[0][0], a0[0], a0[1], a0[2], a0[3], bh[ks][0], bh[ks][1]);
            MMA16816(acc[0][1], a0[0], a0[1], a0[2], a0[3], bh[ks][2], bh[ks][3]);
            MMA16816(acc[1][0], a1[0], a1[1], a1[2], a1[3], bh[ks][0], bh[ks][1]);
            MMA16816(acc[1][1], a1[0], a1[1], a1[2], a1[3], bh[ks][2], bh[ks][3]);
            // hi * lo
            MMA16816(acc[0][0], a0[0], a0[1], a0[2], a0[3], bl[ks][0], bl[ks][1]);
            MMA16816(acc[0][1], a0[0], a0[1], a0[2], a0[3], bl[ks][2], bl[ks][3]);
            MMA16816(acc[1][0], a1[0], a1[1], a1[2], a1[3], bl[ks][0], bl[ks][1]);
            MMA16816(acc[1][1], a1[0], a1[1], a1[2], a1[3], bl[ks][2], bl[ks][3]);
            // lo * hi
            MMA16816(acc[0][0], l0[0], l0[1], l0[2], l0[3], bh[ks][0], bh[ks][1]);
            MMA16816(acc[0][1], l0[0], l0[1], l0[2], l0[3], bh[ks][2], bh[ks][3]);
            MMA16816(acc[1][0], l1[0], l1[1], l1[2], l1[3], bh[ks][0], bh[ks][1]);
            MMA16816(acc[1][1], l1[0], l1[1], l1[2], l1[3], bh[ks][2], bh[ks][3]);
        }

        // ---- epilogue: Poincare MLR arcsinh -> padded SMEM stage ----
        {
            const float* sA = (const float*)(smem + OFF_CA);
            const float* sB = (const float*)(smem + OFF_CB);
            const float* sC = (const float*)(smem + OFF_CC);
            const int cB0 = cb + ((lane & 3) << 1);
            #pragma unroll
            for (int mi = 0; mi < 2; mi++) {
                const int rowA = mi * 16 + (lane >> 2);
                const float L0 = lam[rowA];
                const float L1 = lam[rowA + 8];
                const float M0 = -(L0 - 1.0f), M1 = -(L1 - 1.0f);
                float* s0 = stg + rowA * SSTRIDE;
                float* s1 = s0 + 8 * SSTRIDE;
                #pragma unroll
                for (int ni = 0; ni < 2; ni++) {
                    const float* a = acc[mi][ni];
                    const int c = cB0 + ni * 8;
                    float2 cAv = *(const float2*)(sA + c);
                    float2 cBv = *(const float2*)(sB + c);
                    float2 cCv = *(const float2*)(sC + c);
                    float2 w0, w1;
                    w0.x = cCv.x * asinh_fast(fmaf(L0 * a[0], cAv.x, M0 * cBv.x));
                    w0.y = cCv.y * asinh_fast(fmaf(L0 * a[1], cAv.y, M0 * cBv.y));
                    w1.x = cCv.x * asinh_fast(fmaf(L1 * a[2], cAv.x, M1 * cBv.x));
                    w1.y = cCv.y * asinh_fast(fmaf(L1 * a[3], cAv.y, M1 * cBv.y));
                    *(float2*)(s0 + c) = w0;
                    *(float2*)(s1 + c) = w1;
                }
            }
        }
        __syncthreads();                          // stage tile complete

        // ---- coalesced copy-out: LDS.128 + STG.128, 4 lines per store ----
        {
            const int row = tid >> 3;             // 0..31
            const int ch  = tid & 7;              // 16 floats each
            const float* srow = stg + row * SSTRIDE + ch * 16;
            float* orow = out + ((size_t)t * BM + row) * D + ch * 16;
            #pragma unroll
            for (int q = 0; q < 4; q++)
                *(float4*)(orow + q * 4) = *(const float4*)(srow + q * 4);
        }
        // no trailing sync: next loop-top sync protects stage reuse
    }
}

// ---------------------------------------------------------------------------
extern "C" void kernel_launch(void* const* d_in, const int* in_sizes, int n_in,
                              void* d_out, int out_size) {
    const float* x = (const float*)d_in[0];   // [N, 128]
    const float* z = (const float*)d_in[1];   // [128, 128]
    const float* r = (const float*)d_in[2];   // [128]
    float* out = (float*)d_out;

    int nRows  = in_sizes[0] / D;             // 131072
    int nTiles = nRows / BM;                  // 4096

    int sms = 148;
    cudaDeviceGetAttribute(&sms, cudaDevAttrMultiProcessorCount, 0);
    int grid = 2 * sms;                       // 2 CTAs per SM
    if (grid > nTiles) grid = nTiles;

    cudaFuncSetAttribute(hmlr_fused, cudaFuncAttributeMaxDynamicSharedMemorySize, SMEM_TOTAL);
    hmlr_fused<<<grid, NTHR, SMEM_TOTAL>>>(x, z, r, out, nTiles, grid);
}

// round 15
// speedup vs baseline: 1.2515x; 1.2515x over previous
#include <cuda_runtime.h>
#include <cuda_bf16.h>
#include <cstdint>

#define D       128
#define BM      32          // rows per x tile
#define NTHR    256         // 8 warps
#define RSTRIDE 272         // padded smem row stride (17 x 16B) -> conflict-free ldmatrix

#define XBUF    (BM * RSTRIDE)        // 8704 bytes, one XH or XL tile
#define RAWSZ   (BM * D * 4)          // 16384 bytes raw fp32 tile
// ---------------- smem layout (bytes) ----------------
#define OFF_LAM  0                    // 2 x 32 floats (double-buffered)
#define OFF_CA   256
#define OFF_CB   768
#define OFF_CC   1280
#define OFF_ZSQ  1792
#define OFF_RAW  2304                 // raw fp32 x tiles, 3 x 16KB (triple buffer)
#define OFF_X    (OFF_RAW + 3 * RAWSZ)  // XH0,XL0,XH1,XL1 each XBUF
#define SMEM_TOTAL (OFF_X + 4 * XBUF)   // 86272 B (~84.3 KB) -> 2 CTAs/SM
// Z staging at startup aliases the X region (4*XBUF == one 128x272 Z tile)

__device__ __forceinline__ uint32_t smem_u32(const void* p) {
    uint32_t a;
    asm("{ .reg .u64 t; cvta.to.shared.u64 t, %1; cvt.u32.u64 %0, t; }" : "=r"(a) : "l"(p));
    return a;
}
#define CP_ASYNC16(s, g) \
    asm volatile("cp.async.cg.shared.global [%0], [%1], 16;" :: "r"(s), "l"(g) : "memory")
#define CP_COMMIT() asm volatile("cp.async.commit_group;" ::: "memory")
#define CP_WAIT2()  asm volatile("cp.async.wait_group 2;" ::: "memory")

#define LDMATRIX_X4(r0, r1, r2, r3, a)                                           \
    asm volatile("ldmatrix.sync.aligned.m8n8.x4.shared.b16 {%0,%1,%2,%3}, [%4];" \
                 : "=r"(r0), "=r"(r1), "=r"(r2), "=r"(r3) : "r"(a))

#define MMA16816(d, a0, a1, a2, a3, b0, b1)                                      \
    asm volatile("mma.sync.aligned.m16n8k16.row.col.f32.bf16.bf16.f32 "          \
                 "{%0,%1,%2,%3}, {%4,%5,%6,%7}, {%8,%9}, {%0,%1,%2,%3};"         \
                 : "+f"((d)[0]), "+f"((d)[1]), "+f"((d)[2]), "+f"((d)[3])        \
                 : "r"(a0), "r"(a1), "r"(a2), "r"(a3), "r"(b0), "r"(b1))

__device__ __forceinline__ float sqrt_approx(float v) {
    float o;
    asm("sqrt.approx.f32 %0, %1;" : "=f"(o) : "f"(v));
    return o;
}
__device__ __forceinline__ float asinh_fast(float v) {
    float av = fabsf(v);
    float s  = sqrt_approx(fmaf(av, av, 1.0f));
    float l  = __logf(av + s);
    return copysignf(l, v);
}

// ---------------------------------------------------------------------------
// Persistent fused kernel, 2 CTAs/SM x 8 warps. Warp tile m32 x n16, B hi+lo
// hoisted to regs. RAW triple-buffered (cp.async always 2 tiles ahead), XH/XL
// double-buffered. Direct STG.64 epilogue (staged write-out regressed in R13).
//   inner = xh*zh^T + xh*zl^T + xl*zh^T  (fp32 accum, rel err ~4e-6)
// ---------------------------------------------------------------------------
__global__ __launch_bounds__(NTHR, 2)
void hmlr_fused(const float* __restrict__ x, const float* __restrict__ z,
                const float* __restrict__ r, float* __restrict__ out,
                int nTiles, int step) {
    extern __shared__ unsigned char smem[];
    const uint32_t sb = smem_u32(smem);
    const int tid  = threadIdx.x;
    const int wid  = tid >> 5;
    const int lane = tid & 31;
    const int t0   = blockIdx.x;

    // ---- kick off first three x tile loads (raw triple buffer) ----
    #pragma unroll
    for (int q = 0; q < 3; q++) {
        if (t0 + q * step < nTiles) {
            const char* xg = (const char*)(x + (size_t)(t0 + q * step) * BM * D);
            #pragma unroll
            for (int j = 0; j < 4; j++) {
                uint32_t off = (uint32_t)(tid + j * NTHR) * 16u;
                CP_ASYNC16(sb + OFF_RAW + q * RAWSZ + off, xg + off);
            }
        }
        CP_COMMIT();
    }

    // ---- zero column-norm accumulators ----
    if (tid < D) ((float*)(smem + OFF_ZSQ))[tid] = 0.0f;
    __syncthreads();

    // ---- warp tiling: single m32 row band x 8 col bands of n16 ----
    const int cb = wid << 4;                     // 0..112
    const int g  = lane >> 3, rr = lane & 7;
    const uint32_t offA = (uint32_t)((((g & 1) << 3) + rr) * RSTRIDE + ((g >> 1) << 4));
    const uint32_t offB = (uint32_t)((cb + ((g >> 1) << 3) + rr) * RSTRIDE + ((g & 1) << 4));

    uint32_t bh[8][4], bl[8][4];

    // ---- phase 1: stage ZH (aliases X region) + column norms; hoist bh ----
    {
        const int n  = tid & 127;
        const int kh = tid >> 7;                 // 0..1, 64 k each
        float sq = 0.0f;
        #pragma unroll 8
        for (int kk = 0; kk < 64; kk++) {
            int k = kh * 64 + kk;
            float v = z[(size_t)k * D + n];
            *(__nv_bfloat16*)(smem + OFF_X + n * RSTRIDE + k * 2) = __float2bfloat16_rn(v);
            sq = fmaf(v, v, sq);
        }
        atomicAdd((float*)(smem + OFF_ZSQ) + n, sq);
    }
    __syncthreads();
    {
        const uint32_t bHb = sb + OFF_X + offB;
        #pragma unroll
        for (int ks = 0; ks < 8; ks++)
            LDMATRIX_X4(bh[ks][0], bh[ks][1], bh[ks][2], bh[ks][3], bHb + ks * 32u);
    }
    // per-column constants (ZSQ final after phase-1 barrier)
    if (tid < D) {
        float zn = fmaxf(sqrtf(((const float*)(smem + OFF_ZSQ))[tid]), 1e-15f);
        float t  = 2.0f * r[tid];
        ((float*)(smem + OFF_CA))[tid] = coshf(t) / zn;
        ((float*)(smem + OFF_CB))[tid] = sinhf(t);
        ((float*)(smem + OFF_CC))[tid] = 2.0f * zn;
    }
    __syncthreads();                              // bh hoists done before ZL overwrites

    // ---- phase 2: stage ZL into same region; hoist bl ----
    {
        const int n  = tid & 127;
        const int kh = tid >> 7;
        #pragma unroll 8
        for (int kk = 0; kk < 64; kk++) {
            int k = kh * 64 + kk;
            float v = z[(size_t)k * D + n];
            __nv_bfloat16 h = __float2bfloat16_rn(v);
            float res = v - __bfloat162float(h);
            *(__nv_bfloat16*)(smem + OFF_X + n * RSTRIDE + k * 2) = __float2bfloat16_rn(res);
        }
    }
    __syncthreads();
    {
        const uint32_t bLb = sb + OFF_X + offB;
        #pragma unroll
        for (int ks = 0; ks < 8; ks++)
            LDMATRIX_X4(bl[ks][0], bl[ks][1], bl[ks][2], bl[ks][3], bLb + ks * 32u);
    }
    // loop-top barrier orders these hoist reads before first convert stores

    // ================= persistent tile loop =================
    int p = 0;   // X double-buffer index
    int q = 0;   // raw triple-buffer index
    for (int t = t0; t < nTiles; t += step, p ^= 1, q = (q == 2 ? 0 : q + 1)) {
        const uint32_t rawB = sb + OFF_RAW + (uint32_t)q * RAWSZ;
        const uint32_t xB   = sb + OFF_X + (uint32_t)p * (2u * XBUF);
        float* lam = (float*)(smem + OFF_LAM) + p * 32;

        CP_WAIT2();
        __syncthreads();                          // raw[q] visible; hoist/old reads done

        // ---- convert raw fp32 -> bf16 hi/lo + lambda (X buffer p) ----
        {
            const int row   = tid >> 3;           // 0..31
            const int chunk = tid & 7;            // 16 floats each
            const float4* rp = (const float4*)(smem + (rawB - sb) + row * 512 + chunk * 64);
            float4 v[4];
            v[0] = rp[0]; v[1] = rp[1]; v[2] = rp[2]; v[3] = rp[3];
            float f[16];
            #pragma unroll
            for (int j = 0; j < 4; j++) {
                f[4 * j] = v[j].x; f[4 * j + 1] = v[j].y;
                f[4 * j + 2] = v[j].z; f[4 * j + 3] = v[j].w;
            }
            uint32_t hp[8], lp[8];
            #pragma unroll
            for (int j = 0; j < 8; j++) {
                float a = f[2 * j], b = f[2 * j + 1];
                __nv_bfloat16 ha = __float2bfloat16_rn(a);
                __nv_bfloat16 hb = __float2bfloat16_rn(b);
                float ra = a - __bfloat162float(ha);
                float rc = b - __bfloat162float(hb);
                hp[j] = (uint32_t)__bfloat16_as_ushort(ha) |
                        ((uint32_t)__bfloat16_as_ushort(hb) << 16);
                lp[j] = (uint32_t)__bfloat16_as_ushort(__float2bfloat16_rn(ra)) |
                        ((uint32_t)__bfloat16_as_ushort(__float2bfloat16_rn(rc)) << 16);
            }
            uint32_t doff = (xB - sb) + (uint32_t)(row * RSTRIDE + chunk * 32);
            *(uint4*)(smem + doff)             = make_uint4(hp[0], hp[1], hp[2], hp[3]);
            *(uint4*)(smem + doff + 16)        = make_uint4(hp[4], hp[5], hp[6], hp[7]);
            *(uint4*)(smem + doff + XBUF)      = make_uint4(lp[0], lp[1], lp[2], lp[3]);
            *(uint4*)(smem + doff + XBUF + 16) = make_uint4(lp[4], lp[5], lp[6], lp[7]);

            float sq = 0.0f;
            #pragma unroll
            for (int j = 0; j < 16; j++) sq = fmaf(f[j], f[j], sq);
            sq += __shfl_xor_sync(0xffffffffu, sq, 1);
            sq += __shfl_xor_sync(0xffffffffu, sq, 2);
            sq += __shfl_xor_sync(0xffffffffu, sq, 4);
            if ((lane & 7) == 0) lam[row] = 2.0f / (1.0f - sq);
        }
        __syncthreads();                          // X[p]+lam ready; raw[q] reads done

        // ---- refill raw[q] with tile t+3*step (stays 2 tiles ahead) ----
        if (t + 3 * step < nTiles) {
            const char* xg = (const char*)(x + (size_t)(t + 3 * step) * BM * D);
            #pragma unroll
            for (int j = 0; j < 4; j++) {
                uint32_t off = (uint32_t)(tid + j * NTHR) * 16u;
                CP_ASYNC16(rawB + off, xg + off);
            }
        }
        CP_COMMIT();

        // ---- MMA: A from smem buffer p, B from regs; LDSM interleaved ----
        const uint32_t aH0 = xB + offA;
        const uint32_t aH1 = aH0 + 16 * RSTRIDE;
        const uint32_t aL0 = aH0 + XBUF;
        const uint32_t aL1 = aL0 + 16 * RSTRIDE;

        float acc[2][2][4];
        #pragma unroll
        for (int mi = 0; mi < 2; mi++)
            #pragma unroll
            for (int ni = 0; ni < 2; ni++)
                #pragma unroll
                for (int j = 0; j < 4; j++) acc[mi][ni][j] = 0.0f;

        #pragma unroll
        for (int ks = 0; ks < 8; ks++) {
            const uint32_t kd = (uint32_t)ks * 32u;
            uint32_t a0[4], a1[4], l0[4], l1[4];
            LDMATRIX_X4(a0[0], a0[1], a0[2], a0[3], aH0 + kd);
            LDMATRIX_X4(a1[0], a1[1], a1[2], a1[3], aH1 + kd);
            // hi * hi (covers lo-LDSM latency below)
            MMA16816(acc[0][0], a0[0], a0[1], a0[2], a0[3], bh[ks][0], bh[ks][1]);
            MMA16816(acc[0][1], a0[0], a0[1], a0[2], a0[3], bh[ks][2], bh[ks][3]);
            LDMATRIX_X4(l0[0], l0[1], l0[2], l0[3], aL0 + kd);
            MMA16816(acc[1][0], a1[0], a1[1], a1[2], a1[3], bh[ks][0], bh[ks][1]);
            MMA16816(acc[1][1], a1[0], a1[1], a1[2], a1[3], bh[ks][2], bh[ks][3]);
            LDMATRIX_X4(l1[0], l1[1], l1[2], l1[3], aL1 + kd);
            // hi * lo
            MMA16816(acc[0][0], a0[0], a0[1], a0[2], a0[3], bl[ks][0], bl[ks][1]);
            MMA16816(acc[0][1], a0[0], a0[1], a0[2], a0[3], bl[ks][2], bl[ks][3]);
            MMA16816(acc[1][0], a1[0], a1[1], a1[2], a1[3], bl[ks][0], bl[ks][1]);
            MMA16816(acc[1][1], a1[0], a1[1], a1[2], a1[3], bl[ks][2], bl[ks][3]);
            // lo * hi
            MMA16816(acc[0][0], l0[0], l0[1], l0[2], l0[3], bh[ks][0], bh[ks][1]);
            MMA16816(acc[0][1], l0[0], l0[1], l0[2], l0[3], bh[ks][2], bh[ks][3]);
            MMA16816(acc[1][0], l1[0], l1[1], l1[2], l1[3], bh[ks][0], bh[ks][1]);
            MMA16816(acc[1][1], l1[0], l1[1], l1[2], l1[3], bh[ks][2], bh[ks][3]);
        }

        // ---- epilogue: Poincare MLR arcsinh, direct fp32 out ----
        {
            const float* sA = (const float*)(smem + OFF_CA);
            const float* sB = (const float*)(smem + OFF_CB);
            const float* sC = (const float*)(smem + OFF_CC);
            const int cB0 = cb + ((lane & 3) << 1);
            #pragma unroll
            for (int mi = 0; mi < 2; mi++) {
                const int rowA = mi * 16 + (lane >> 2);
                const float L0 = lam[rowA];
                const float L1 = lam[rowA + 8];
                const float M0 = -(L0 - 1.0f), M1 = -(L1 - 1.0f);
                float* o0 = out + ((size_t)t * BM + rowA) * D;
                float* o1 = o0 + 8 * D;
                #pragma unroll
                for (int ni = 0; ni < 2; ni++) {
                    const float* a = acc[mi][ni];
                    const int c = cB0 + ni * 8;
                    float2 cAv = *(const float2*)(sA + c);
                    float2 cBv = *(const float2*)(sB + c);
                    float2 cCv = *(const float2*)(sC + c);
                    float2 w0, w1;
                    w0.x = cCv.x * asinh_fast(fmaf(L0 * a[0], cAv.x, M0 * cBv.x));
                    w0.y = cCv.y * asinh_fast(fmaf(L0 * a[1], cAv.y, M0 * cBv.y));
                    w1.x = cCv.x * asinh_fast(fmaf(L1 * a[2], cAv.x, M1 * cBv.x));
                    w1.y = cCv.y * asinh_fast(fmaf(L1 * a[3], cAv.y, M1 * cBv.y));
                    *(float2*)(o0 + c) = w0;
                    *(float2*)(o1 + c) = w1;
                }
            }
        }
        // no trailing sync: next convert writes X buffer p^1, raw q+1
    }
}

// ---------------------------------------------------------------------------
extern "C" void kernel_launch(void* const* d_in, const int* in_sizes, int n_in,
                              void* d_out, int out_size) {
    const float* x = (const float*)d_in[0];   // [N, 128]
    const float* z = (const float*)d_in[1];   // [128, 128]
    const float* r = (const float*)d_in[2];   // [128]
    float* out = (float*)d_out;

    int nRows  = in_sizes[0] / D;             // 131072
    int nTiles = nRows / BM;                  // 4096

    int sms = 148;
    cudaDeviceGetAttribute(&sms, cudaDevAttrMultiProcessorCount, 0);
    int grid = 2 * sms;                       // 2 CTAs per SM
    if (grid > nTiles) grid = nTiles;

    cudaFuncSetAttribute(hmlr_fused, cudaFuncAttributeMaxDynamicSharedMemorySize, SMEM_TOTAL);
    hmlr_fused<<<grid, NTHR, SMEM_TOTAL>>>(x, z, r, out, nTiles, grid);
}

// round 16
// speedup vs baseline: 1.3368x; 1.0681x over previous
#include <cuda_runtime.h>
#include <cuda_bf16.h>
#include <cstdint>

#define D       128
#define BM      32          // rows per x tile
#define NTHR    256         // 8 warps
#define RSTRIDE 272         // padded smem row stride (17 x 16B) -> conflict-free ldmatrix

#define XBUF    (BM * RSTRIDE)        // 8704 bytes, one XH or XL tile
#define RAWSZ   (BM * D * 4)          // 16384 bytes raw fp32 tile
#define ZBUF    (D * RSTRIDE)         // 34816 bytes, one z tile
// ---------------- smem layout (bytes) ----------------
#define OFF_LAM  0                    // 32 floats
#define OFF_CA   128
#define OFF_CB   640
#define OFF_CC   1152
#define OFF_ZSQ  1664
#define OFF_RAW  2176                 // raw fp32 x tile (single buffer)
#define OFF_X    (OFF_RAW + RAWSZ)    // XH then XL (single buffer)
#define OFF_ZL   (OFF_X + 2 * XBUF)   // resident zl tile (bl read per k-step)
#define SMEM_TOTAL (OFF_ZL + ZBUF)    // 70784 B (~69.1 KB) -> 3 CTAs/SM

__device__ __forceinline__ uint32_t smem_u32(const void* p) {
    uint32_t a;
    asm("{ .reg .u64 t; cvta.to.shared.u64 t, %1; cvt.u32.u64 %0, t; }" : "=r"(a) : "l"(p));
    return a;
}
#define CP_ASYNC16(s, g) \
    asm volatile("cp.async.cg.shared.global [%0], [%1], 16;" :: "r"(s), "l"(g) : "memory")
#define CP_COMMIT() asm volatile("cp.async.commit_group;" ::: "memory")
#define CP_WAIT0()  asm volatile("cp.async.wait_group 0;" ::: "memory")

#define LDMATRIX_X4(r0, r1, r2, r3, a)                                           \
    asm volatile("ldmatrix.sync.aligned.m8n8.x4.shared.b16 {%0,%1,%2,%3}, [%4];" \
                 : "=r"(r0), "=r"(r1), "=r"(r2), "=r"(r3) : "r"(a))

#define MMA16816(d, a0, a1, a2, a3, b0, b1)                                      \
    asm volatile("mma.sync.aligned.m16n8k16.row.col.f32.bf16.bf16.f32 "          \
                 "{%0,%1,%2,%3}, {%4,%5,%6,%7}, {%8,%9}, {%0,%1,%2,%3};"         \
                 : "+f"((d)[0]), "+f"((d)[1]), "+f"((d)[2]), "+f"((d)[3])        \
                 : "r"(a0), "r"(a1), "r"(a2), "r"(a3), "r"(b0), "r"(b1))

__device__ __forceinline__ float sqrt_approx(float v) {
    float o;
    asm("sqrt.approx.f32 %0, %1;" : "=f"(o) : "f"(v));
    return o;
}
__device__ __forceinline__ float asinh_fast(float v) {
    float av = fabsf(v);
    float s  = sqrt_approx(fmaf(av, av, 1.0f));
    float l  = __logf(av + s);
    return copysignf(l, v);
}

// ---------------------------------------------------------------------------
// Persistent fused kernel, 3 CTAs/SM x 8 warps (24 warps/SM). Warp tile
// m32 x n16. bh hoisted in regs (32); bl re-read from resident ZL smem tile
// each k-step (traffic-for-occupancy trade). Single raw + single X buffer;
// the loop-top barrier orders old X reads vs new X writes -> 2 syncs/tile.
//   inner = xh*zh^T + xh*zl^T + xl*zh^T  (fp32 accum, rel err ~4e-6)
// ---------------------------------------------------------------------------
__global__ __launch_bounds__(NTHR, 3)
void hmlr_fused(const float* __restrict__ x, const float* __restrict__ z,
                const float* __restrict__ r, float* __restrict__ out,
                int nTiles, int step) {
    extern __shared__ unsigned char smem[];
    const uint32_t sb = smem_u32(smem);
    const int tid  = threadIdx.x;
    const int wid  = tid >> 5;
    const int lane = tid & 31;
    const int t0   = blockIdx.x;

    // ---- kick off first x tile load ----
    if (t0 < nTiles) {
        const char* xg = (const char*)(x + (size_t)t0 * BM * D);
        #pragma unroll
        for (int j = 0; j < 4; j++) {
            uint32_t off = (uint32_t)(tid + j * NTHR) * 16u;
            CP_ASYNC16(sb + OFF_RAW + off, xg + off);
        }
    }
    CP_COMMIT();

    // ---- zero column-norm accumulators ----
    if (tid < D) ((float*)(smem + OFF_ZSQ))[tid] = 0.0f;
    __syncthreads();

    // ---- warp tiling: single m32 row band x 8 col bands of n16 ----
    const int cb = wid << 4;                     // 0..112
    const int g  = lane >> 3, rr = lane & 7;
    const uint32_t offA = (uint32_t)((((g & 1) << 3) + rr) * RSTRIDE + ((g >> 1) << 4));
    const uint32_t offB = (uint32_t)((cb + ((g >> 1) << 3) + rr) * RSTRIDE + ((g & 1) << 4));

    uint32_t bh[8][4];

    // ---- phase 1: stage ZH into the ZL slot + column norms; hoist bh ----
    {
        const int n  = tid & 127;
        const int kh = tid >> 7;                 // 0..1, 64 k each
        float sq = 0.0f;
        #pragma unroll 8
        for (int kk = 0; kk < 64; kk++) {
            int k = kh * 64 + kk;
            float v = z[(size_t)k * D + n];
            *(__nv_bfloat16*)(smem + OFF_ZL + n * RSTRIDE + k * 2) = __float2bfloat16_rn(v);
            sq = fmaf(v, v, sq);
        }
        atomicAdd((float*)(smem + OFF_ZSQ) + n, sq);
    }
    __syncthreads();
    {
        const uint32_t bHb = sb + OFF_ZL + offB;
        #pragma unroll
        for (int ks = 0; ks < 8; ks++)
            LDMATRIX_X4(bh[ks][0], bh[ks][1], bh[ks][2], bh[ks][3], bHb + ks * 32u);
    }
    // per-column constants (ZSQ final after phase-1 barrier)
    if (tid < D) {
        float zn = fmaxf(sqrtf(((const float*)(smem + OFF_ZSQ))[tid]), 1e-15f);
        float t  = 2.0f * r[tid];
        ((float*)(smem + OFF_CA))[tid] = coshf(t) / zn;
        ((float*)(smem + OFF_CB))[tid] = sinhf(t);
        ((float*)(smem + OFF_CC))[tid] = 2.0f * zn;
    }
    __syncthreads();                              // bh hoists done before ZL overwrite

    // ---- phase 2: fill ZL with the lo residuals (resident for whole kernel) ----
    {
        const int n  = tid & 127;
        const int kh = tid >> 7;
        #pragma unroll 8
        for (int kk = 0; kk < 64; kk++) {
            int k = kh * 64 + kk;
            float v = z[(size_t)k * D + n];
            __nv_bfloat16 h = __float2bfloat16_rn(v);
            float res = v - __bfloat162float(h);
            *(__nv_bfloat16*)(smem + OFF_ZL + n * RSTRIDE + k * 2) = __float2bfloat16_rn(res);
        }
    }
    // loop-top barrier publishes ZL before first k-loop reads it

    const uint32_t aH0 = sb + OFF_X + offA;
    const uint32_t aH1 = aH0 + 16 * RSTRIDE;
    const uint32_t aL0 = aH0 + XBUF;
    const uint32_t aL1 = aL0 + 16 * RSTRIDE;
    const uint32_t blB = sb + OFF_ZL + offB;
    float* lam = (float*)(smem + OFF_LAM);

    // ================= persistent tile loop =================
    for (int t = t0; t < nTiles; t += step) {
        CP_WAIT0();
        __syncthreads();          // raw visible; prior X/lam reads + ZL writes ordered

        // ---- convert raw fp32 -> bf16 hi/lo + lambda ----
        {
            const int row   = tid >> 3;           // 0..31
            const int chunk = tid & 7;            // 16 floats each
            const float4* rp = (const float4*)(smem + OFF_RAW + row * 512 + chunk * 64);
            float4 v[4];
            v[0] = rp[0]; v[1] = rp[1]; v[2] = rp[2]; v[3] = rp[3];
            float f[16];
            #pragma unroll
            for (int j = 0; j < 4; j++) {
                f[4 * j] = v[j].x; f[4 * j + 1] = v[j].y;
                f[4 * j + 2] = v[j].z; f[4 * j + 3] = v[j].w;
            }
            uint32_t hp[8], lp[8];
            #pragma unroll
            for (int j = 0; j < 8; j++) {
                float a = f[2 * j], b = f[2 * j + 1];
                __nv_bfloat16 ha = __float2bfloat16_rn(a);
                __nv_bfloat16 hb = __float2bfloat16_rn(b);
                float ra = a - __bfloat162float(ha);
                float rc = b - __bfloat162float(hb);
                hp[j] = (uint32_t)__bfloat16_as_ushort(ha) |
                        ((uint32_t)__bfloat16_as_ushort(hb) << 16);
                lp[j] = (uint32_t)__bfloat16_as_ushort(__float2bfloat16_rn(ra)) |
                        ((uint32_t)__bfloat16_as_ushort(__float2bfloat16_rn(rc)) << 16);
            }
            uint32_t doff = OFF_X + (uint32_t)(row * RSTRIDE + chunk * 32);
            *(uint4*)(smem + doff)             = make_uint4(hp[0], hp[1], hp[2], hp[3]);
            *(uint4*)(smem + doff + 16)        = make_uint4(hp[4], hp[5], hp[6], hp[7]);
            *(uint4*)(smem + doff + XBUF)      = make_uint4(lp[0], lp[1], lp[2], lp[3]);
            *(uint4*)(smem + doff + XBUF + 16) = make_uint4(lp[4], lp[5], lp[6], lp[7]);

            float sq = 0.0f;
            #pragma unroll
            for (int j = 0; j < 16; j++) sq = fmaf(f[j], f[j], sq);
            sq += __shfl_xor_sync(0xffffffffu, sq, 1);
            sq += __shfl_xor_sync(0xffffffffu, sq, 2);
            sq += __shfl_xor_sync(0xffffffffu, sq, 4);
            if ((lane & 7) == 0) lam[row] = 2.0f / (1.0f - sq);
        }
        __syncthreads();                          // X+lam ready; raw reads done

        // ---- prefetch next tile into raw (lands during MMA phase) ----
        if (t + step < nTiles) {
            const char* xg = (const char*)(x + (size_t)(t + step) * BM * D);
            #pragma unroll
            for (int j = 0; j < 4; j++) {
                uint32_t off = (uint32_t)(tid + j * NTHR) * 16u;
                CP_ASYNC16(sb + OFF_RAW + off, xg + off);
            }
        }
        CP_COMMIT();

        // ---- MMA: A + bl from smem, bh from regs; 12 HMMA per ks ----
        float acc[2][2][4];
        #pragma unroll
        for (int mi = 0; mi < 2; mi++)
            #pragma unroll
            for (int ni = 0; ni < 2; ni++)
                #pragma unroll
                for (int j = 0; j < 4; j++) acc[mi][ni][j] = 0.0f;

        #pragma unroll
        for (int ks = 0; ks < 8; ks++) {
            const uint32_t kd = (uint32_t)ks * 32u;
            uint32_t a0[4], a1[4], l0[4], l1[4], bf[4];
            LDMATRIX_X4(a0[0], a0[1], a0[2], a0[3], aH0 + kd);
            LDMATRIX_X4(a1[0], a1[1], a1[2], a1[3], aH1 + kd);
            // hi * hi (covers the following LDSM latencies)
            MMA16816(acc[0][0], a0[0], a0[1], a0[2], a0[3], bh[ks][0], bh[ks][1]);
            MMA16816(acc[0][1], a0[0], a0[1], a0[2], a0[3], bh[ks][2], bh[ks][3]);
            LDMATRIX_X4(bf[0], bf[1], bf[2], bf[3], blB + kd);
            MMA16816(acc[1][0], a1[0], a1[1], a1[2], a1[3], bh[ks][0], bh[ks][1]);
            MMA16816(acc[1][1], a1[0], a1[1], a1[2], a1[3], bh[ks][2], bh[ks][3]);
            LDMATRIX_X4(l0[0], l0[1], l0[2], l0[3], aL0 + kd);
            LDMATRIX_X4(l1[0], l1[1], l1[2], l1[3], aL1 + kd);
            // hi * lo
            MMA16816(acc[0][0], a0[0], a0[1], a0[2], a0[3], bf[0], bf[1]);
            MMA16816(acc[0][1], a0[0], a0[1], a0[2], a0[3], bf[2], bf[3]);
            MMA16816(acc[1][0], a1[0], a1[1], a1[2], a1[3], bf[0], bf[1]);
            MMA16816(acc[1][1], a1[0], a1[1], a1[2], a1[3], bf[2], bf[3]);
            // lo * hi
            MMA16816(acc[0][0], l0[0], l0[1], l0[2], l0[3], bh[ks][0], bh[ks][1]);
            MMA16816(acc[0][1], l0[0], l0[1], l0[2], l0[3], bh[ks][2], bh[ks][3]);
            MMA16816(acc[1][0], l1[0], l1[1], l1[2], l1[3], bh[ks][0], bh[ks][1]);
            MMA16816(acc[1][1], l1[0], l1[1], l1[2], l1[3], bh[ks][2], bh[ks][3]);
        }

        // ---- epilogue: Poincare MLR arcsinh, direct fp32 out ----
        {
            const float* sA = (const float*)(smem + OFF_CA);
            const float* sB = (const float*)(smem + OFF_CB);
            const float* sC = (const float*)(smem + OFF_CC);
            const int cB0 = cb + ((lane & 3) << 1);
            #pragma unroll
            for (int mi = 0; mi < 2; mi++) {
                const int rowA = mi * 16 + (lane >> 2);
                const float L0 = lam[rowA];
                const float L1 = lam[rowA + 8];
                const float M0 = -(L0 - 1.0f), M1 = -(L1 - 1.0f);
                float* o0 = out + ((size_t)t * BM + rowA) * D;
                float* o1 = o0 + 8 * D;
                #pragma unroll
                for (int ni = 0; ni < 2; ni++) {
                    const float* a = acc[mi][ni];
                    const int c = cB0 + ni * 8;
                    float2 cAv = *(const float2*)(sA + c);
                    float2 cBv = *(const float2*)(sB + c);
                    float2 cCv = *(const float2*)(sC + c);
                    float2 w0, w1;
                    w0.x = cCv.x * asinh_fast(fmaf(L0 * a[0], cAv.x, M0 * cBv.x));
                    w0.y = cCv.y * asinh_fast(fmaf(L0 * a[1], cAv.y, M0 * cBv.y));
                    w1.x = cCv.x * asinh_fast(fmaf(L1 * a[2], cAv.x, M1 * cBv.x));
                    w1.y = cCv.y * asinh_fast(fmaf(L1 * a[3], cAv.y, M1 * cBv.y));
                    *(float2*)(o0 + c) = w0;
                    *(float2*)(o1 + c) = w1;
                }
            }
        }
        // no trailing sync: loop-top barrier orders X reuse
    }
}

// ---------------------------------------------------------------------------
extern "C" void kernel_launch(void* const* d_in, const int* in_sizes, int n_in,
                              void* d_out, int out_size) {
    const float* x = (const float*)d_in[0];   // [N, 128]
    const float* z = (const float*)d_in[1];   // [128, 128]
    const float* r = (const float*)d_in[2];   // [128]
    float* out = (float*)d_out;

    int nRows  = in_sizes[0] / D;             // 131072
    int nTiles = nRows / BM;                  // 4096

    int sms = 148;
    cudaDeviceGetAttribute(&sms, cudaDevAttrMultiProcessorCount, 0);
    int grid = 3 * sms;                       // 3 CTAs per SM
    if (grid > nTiles) grid = nTiles;

    cudaFuncSetAttribute(hmlr_fused, cudaFuncAttributeMaxDynamicSharedMemorySize, SMEM_TOTAL);
    hmlr_fused<<<grid, NTHR, SMEM_TOTAL>>>(x, z, r, out, nTiles, grid);
}